// round 1
// baseline (speedup 1.0000x reference)
#include <cuda_runtime.h>
#include <math.h>

#define BB 4
#define TT 256
#define UU 64
#define DD 640
#define HH 640
#define VV 1024

#define MROWS 32
#define KB 8

// Scratch for projected encoder / predictor (no runtime allocation allowed)
__device__ float g_enc[BB * TT * HH];   // (B*T, H) = 1024 x 640
__device__ float g_pred[BB * UU * HH];  // (B*U, H) = 256 x 640

// ---------------------------------------------------------------------------
// Kernel A: C[M][HH] = X[M][DD] @ W[DD][HH] + bias   (M = 1024 or 256)
// BM=BN=64, BK=16, 256 threads, 4x4 micro-tile per thread.
// ---------------------------------------------------------------------------
__global__ __launch_bounds__(256) void proj_gemm(const float* __restrict__ X,
                                                 const float* __restrict__ W,
                                                 const float* __restrict__ bias,
                                                 int which) {
    float* C = which ? g_pred : g_enc;
    __shared__ float As[16][65];  // [kk][row], padded
    __shared__ float Bs[16][65];  // [kk][col], padded

    const int tid = threadIdx.x;
    const int bm = blockIdx.x * 64;
    const int bn = blockIdx.y * 64;
    const int ty = tid / 16, tx = tid % 16;

    float c[4][4];
#pragma unroll
    for (int i = 0; i < 4; i++)
#pragma unroll
        for (int j = 0; j < 4; j++) c[i][j] = 0.f;

    for (int k0 = 0; k0 < DD; k0 += 16) {
        for (int l = tid; l < 64 * 16; l += 256) {
            int row = l >> 4, kk = l & 15;
            As[kk][row] = X[(size_t)(bm + row) * DD + k0 + kk];
        }
        for (int l = tid; l < 16 * 64; l += 256) {
            int kk = l >> 6, col = l & 63;
            Bs[kk][col] = W[(size_t)(k0 + kk) * HH + bn + col];
        }
        __syncthreads();
#pragma unroll
        for (int kk = 0; kk < 16; kk++) {
            float a[4], b[4];
#pragma unroll
            for (int i = 0; i < 4; i++) a[i] = As[kk][ty * 4 + i];
#pragma unroll
            for (int j = 0; j < 4; j++) b[j] = Bs[kk][tx * 4 + j];
#pragma unroll
            for (int i = 0; i < 4; i++)
#pragma unroll
                for (int j = 0; j < 4; j++) c[i][j] += a[i] * b[j];
        }
        __syncthreads();
    }
#pragma unroll
    for (int i = 0; i < 4; i++)
#pragma unroll
        for (int j = 0; j < 4; j++)
            C[(size_t)(bm + ty * 4 + i) * HH + bn + tx * 4 + j] =
                c[i][j] + bias[bn + tx * 4 + j];
}

// fast tanh: 1 - 2/(exp(2x)+1); exact saturation at +/-inf via __expf/__fdividef
__device__ __forceinline__ float ftanh(float x) {
    float e = __expf(2.f * x);
    return 1.f - __fdividef(2.f, e + 1.f);
}

// ---------------------------------------------------------------------------
// Kernel B: fused joint + GEMM + log_softmax.
// One CTA handles MROWS=32 consecutive (b,t,u) rows x full V=1024.
// Since U=64 and MROWS=32, all rows of a CTA share one encoder row.
// Thread layout: ry = tid/64 (4 row groups of 8 rows), tx = tid%64.
// Per-thread tile: 8 rows x 16 cols (cols = tx*4 + 256*g + m).
// ---------------------------------------------------------------------------
__global__ __launch_bounds__(256, 1) void joint_kernel(const float* __restrict__ Wfc,
                                                       const float* __restrict__ bfc,
                                                       float* __restrict__ out) {
    extern __shared__ float sm[];
    float* jointS = sm;                 // MROWS*HH = 20480 floats
    float* wS = sm + MROWS * HH;        // KB*VV   =  8192 floats
    __shared__ float wred[8][8];        // [warp][row_i]

    const int tid = threadIdx.x;
    const int r0 = blockIdx.x * MROWS;
    const int b = r0 / (TT * UU);
    const int encrow = r0 / UU;         // constant over the 32 rows
    const int u0 = r0 % UU;

    const float* enc = g_enc + (size_t)encrow * HH;
    const float* pred = g_pred + ((size_t)b * UU + u0) * HH;

    // Phase 1: joint tile -> SMEM
    for (int e = tid; e < MROWS * HH; e += 256) {
        int i = e / HH;
        int h = e - i * HH;
        jointS[e] = ftanh(enc[h] + pred[(size_t)i * HH + h]);
    }

    const int ry = tid >> 6;   // 0..3
    const int tx = tid & 63;   // 0..63

    float v[8][16];
#pragma unroll
    for (int i = 0; i < 8; i++)
#pragma unroll
        for (int j = 0; j < 16; j++) v[i][j] = 0.f;

    // Preload W tile 0 and commit to SMEM
    float4 pre[8];
    {
        const float4* src = reinterpret_cast<const float4*>(Wfc);
#pragma unroll
        for (int q = 0; q < 8; q++) pre[q] = src[tid + 256 * q];
        float4* dst = reinterpret_cast<float4*>(wS);
#pragma unroll
        for (int q = 0; q < 8; q++) dst[tid + 256 * q] = pre[q];
    }
    __syncthreads();  // covers jointS + wS

    for (int k0 = 0; k0 < HH; k0 += KB) {
        const bool more = (k0 + KB) < HH;
        if (more) {
            const float4* src =
                reinterpret_cast<const float4*>(Wfc + (size_t)(k0 + KB) * VV);
#pragma unroll
            for (int q = 0; q < 8; q++) pre[q] = src[tid + 256 * q];
        }
#pragma unroll
        for (int kk = 0; kk < KB; kk++) {
            float a[8];
#pragma unroll
            for (int i = 0; i < 8; i++)
                a[i] = jointS[(ry * 8 + i) * HH + k0 + kk];  // warp broadcast
            const float4* wrow = reinterpret_cast<const float4*>(wS + kk * VV);
            float4 b0 = wrow[tx];
            float4 b1 = wrow[tx + 64];
            float4 b2 = wrow[tx + 128];
            float4 b3 = wrow[tx + 192];
            float bb[16] = {b0.x, b0.y, b0.z, b0.w, b1.x, b1.y, b1.z, b1.w,
                            b2.x, b2.y, b2.z, b2.w, b3.x, b3.y, b3.z, b3.w};
#pragma unroll
            for (int i = 0; i < 8; i++)
#pragma unroll
                for (int j = 0; j < 16; j++) v[i][j] += a[i] * bb[j];
        }
        __syncthreads();
        if (more) {
            float4* dst = reinterpret_cast<float4*>(wS);
#pragma unroll
            for (int q = 0; q < 8; q++) dst[tid + 256 * q] = pre[q];
        }
        __syncthreads();
    }

    // Bias
    {
        const float4* bv = reinterpret_cast<const float4*>(bfc);
        float biasv[16];
#pragma unroll
        for (int g = 0; g < 4; g++) {
            float4 bg = bv[tx + 64 * g];
            biasv[4 * g + 0] = bg.x;
            biasv[4 * g + 1] = bg.y;
            biasv[4 * g + 2] = bg.z;
            biasv[4 * g + 3] = bg.w;
        }
#pragma unroll
        for (int i = 0; i < 8; i++)
#pragma unroll
            for (int j = 0; j < 16; j++) v[i][j] += biasv[j];
    }

    const int w = tid >> 5;  // warp 0..7; warps (2*ry, 2*ry+1) share rows

    // Row max
    float rmax[8];
#pragma unroll
    for (int i = 0; i < 8; i++) {
        float m = v[i][0];
#pragma unroll
        for (int j = 1; j < 16; j++) m = fmaxf(m, v[i][j]);
#pragma unroll
        for (int off = 16; off; off >>= 1)
            m = fmaxf(m, __shfl_xor_sync(0xffffffffu, m, off));
        if ((tid & 31) == 0) wred[w][i] = m;
    }
    __syncthreads();
#pragma unroll
    for (int i = 0; i < 8; i++)
        rmax[i] = fmaxf(wred[2 * ry][i], wred[2 * ry + 1][i]);
    __syncthreads();

    // Row sum of exp
    float rls[8];
#pragma unroll
    for (int i = 0; i < 8; i++) {
        float s = 0.f;
#pragma unroll
        for (int j = 0; j < 16; j++) s += __expf(v[i][j] - rmax[i]);
#pragma unroll
        for (int off = 16; off; off >>= 1)
            s += __shfl_xor_sync(0xffffffffu, s, off);
        if ((tid & 31) == 0) wred[w][i] = s;
    }
    __syncthreads();
#pragma unroll
    for (int i = 0; i < 8; i++)
        rls[i] = logf(wred[2 * ry][i] + wred[2 * ry + 1][i]) + rmax[i];

    // Write log-softmax output (float4, coalesced)
#pragma unroll
    for (int i = 0; i < 8; i++) {
        float4* orow = reinterpret_cast<float4*>(out + (size_t)(r0 + ry * 8 + i) * VV);
#pragma unroll
        for (int g = 0; g < 4; g++) {
            float4 o;
            o.x = v[i][4 * g + 0] - rls[i];
            o.y = v[i][4 * g + 1] - rls[i];
            o.z = v[i][4 * g + 2] - rls[i];
            o.w = v[i][4 * g + 3] - rls[i];
            orow[tx + 64 * g] = o;
        }
    }
}

// ---------------------------------------------------------------------------
extern "C" void kernel_launch(void* const* d_in, const int* in_sizes, int n_in,
                              void* d_out, int out_size) {
    const float* enc_out = (const float*)d_in[0];
    const float* pred_out = (const float*)d_in[1];
    const float* W_enc = (const float*)d_in[2];
    const float* b_enc = (const float*)d_in[3];
    const float* W_pred = (const float*)d_in[4];
    const float* b_pred = (const float*)d_in[5];
    const float* W_fc = (const float*)d_in[6];
    const float* b_fc = (const float*)d_in[7];
    float* out = (float*)d_out;

    const size_t smemB = (size_t)(MROWS * HH + KB * VV) * sizeof(float);  // 114688
    cudaFuncSetAttribute(joint_kernel, cudaFuncAttributeMaxDynamicSharedMemorySize,
                         (int)smemB);

    dim3 gEnc((BB * TT) / 64, HH / 64);
    proj_gemm<<<gEnc, 256>>>(enc_out, W_enc, b_enc, 0);
    dim3 gPred((BB * UU) / 64, HH / 64);
    proj_gemm<<<gPred, 256>>>(pred_out, W_pred, b_pred, 1);

    joint_kernel<<<(BB * TT * UU) / MROWS, 256, smemB>>>(W_fc, b_fc, out);
}

// round 2
// speedup vs baseline: 2.3325x; 2.3325x over previous
#include <cuda_runtime.h>
#include <cuda_fp16.h>
#include <math.h>

#define BB 4
#define TT 256
#define UU 64
#define DD 640
#define HH 640
#define VV 1024
#define MTOT (BB*TT*UU)   // 65536

#define AROW 648          // padded f16 per A row in SMEM (conflict-free frag LDS)
#define BROW 24           // padded f16 per B row in SMEM
#define KT 40             // 640/16 k-steps
#define L2E 1.4426950408889634f

// ---- static device scratch (no runtime allocation allowed) ----
__device__ float  g_enc[BB*TT*HH];
__device__ float  g_pred[BB*UU*HH];
__device__ float  g_part[5*BB*TT*HH];
__device__ float  g_partp[5*BB*UU*HH];
__device__ __half g_w16t[VV*HH];                 // W_fc^T as f16: [n][k]
__device__ __half g_joint[(size_t)MTOT*HH];      // tanh(enc+pred) f16, 84MB
__device__ __half g_logits[(size_t)MTOT*VV];     // unnormalized logits f16, 128MB

// ===========================================================================
// W_fc fp32 [k][n] -> f16 transposed [n][k]
// ===========================================================================
__global__ __launch_bounds__(256) void convert_wfc(const float* __restrict__ Wfc) {
    __shared__ float t[32][33];
    int n0 = blockIdx.x * 32, k0 = blockIdx.y * 32;
    int tx = threadIdx.x & 31, ty = threadIdx.x >> 5;  // ty 0..7
#pragma unroll
    for (int j = 0; j < 4; j++)
        t[ty + 8 * j][tx] = Wfc[(size_t)(k0 + ty + 8 * j) * VV + n0 + tx];
    __syncthreads();
#pragma unroll
    for (int j = 0; j < 4; j++)
        g_w16t[(size_t)(n0 + ty + 8 * j) * HH + k0 + tx] =
            __float2half(t[tx][ty + 8 * j]);
}

// ===========================================================================
// Projection GEMM, split-K by 5 (each z handles 128 of K=640), partials out.
// BM=BN=64, BK=16, 256 threads, 4x4 micro-tile.
// ===========================================================================
__global__ __launch_bounds__(256) void proj_gemm(const float* __restrict__ X,
                                                 const float* __restrict__ W,
                                                 int which) {
    float* C = which ? g_partp : g_part;
    const int Mrows = which ? (BB * UU) : (BB * TT);
    __shared__ float As[16][65];
    __shared__ float Bs[16][65];

    const int tid = threadIdx.x;
    const int bm = blockIdx.x * 64;
    const int bn = blockIdx.y * 64;
    const int kz = blockIdx.z;
    const int ty = tid / 16, tx = tid % 16;

    float c[4][4];
#pragma unroll
    for (int i = 0; i < 4; i++)
#pragma unroll
        for (int j = 0; j < 4; j++) c[i][j] = 0.f;

    for (int k0 = kz * 128; k0 < kz * 128 + 128; k0 += 16) {
        for (int l = tid; l < 64 * 16; l += 256) {
            int row = l >> 4, kk = l & 15;
            As[kk][row] = X[(size_t)(bm + row) * DD + k0 + kk];
        }
        for (int l = tid; l < 16 * 64; l += 256) {
            int kk = l >> 6, col = l & 63;
            Bs[kk][col] = W[(size_t)(k0 + kk) * HH + bn + col];
        }
        __syncthreads();
#pragma unroll
        for (int kk = 0; kk < 16; kk++) {
            float a[4], b[4];
#pragma unroll
            for (int i = 0; i < 4; i++) a[i] = As[kk][ty * 4 + i];
#pragma unroll
            for (int j = 0; j < 4; j++) b[j] = Bs[kk][tx * 4 + j];
#pragma unroll
            for (int i = 0; i < 4; i++)
#pragma unroll
                for (int j = 0; j < 4; j++) c[i][j] += a[i] * b[j];
        }
        __syncthreads();
    }
    float* Cz = C + (size_t)kz * Mrows * HH;
#pragma unroll
    for (int i = 0; i < 4; i++)
#pragma unroll
        for (int j = 0; j < 4; j++)
            Cz[(size_t)(bm + ty * 4 + i) * HH + bn + tx * 4 + j] = c[i][j];
}

__global__ __launch_bounds__(256) void proj_reduce(const float* __restrict__ b_enc,
                                                   const float* __restrict__ b_pred) {
    int idx = blockIdx.x * 256 + threadIdx.x;
    const int encN = BB * TT * HH;
    const int predN = BB * UU * HH;
    if (idx < encN) {
        float s = b_enc[idx % HH];
#pragma unroll
        for (int z = 0; z < 5; z++) s += g_part[(size_t)z * encN + idx];
        g_enc[idx] = s;
    } else {
        int j = idx - encN;
        if (j < predN) {
            float s = b_pred[j % HH];
#pragma unroll
            for (int z = 0; z < 5; z++) s += g_partp[(size_t)z * predN + j];
            g_pred[j] = s;
        }
    }
}

// ===========================================================================
// Joint tanh: g_joint[r][h] = f16(tanh(enc[r/64][h] + pred[...][h]))
// One CTA = 32 consecutive rows (share one enc row).
// ===========================================================================
__global__ __launch_bounds__(256) void tanh_joint() {
    const int r0 = blockIdx.x * 32;
    const float* enc = g_enc + (size_t)(r0 / UU) * HH;
    const float* pred = g_pred + ((size_t)(r0 / (TT * UU)) * UU + (r0 % UU)) * HH;

    for (int p = threadIdx.x; p < 32 * (HH / 2); p += 256) {
        int i = p / (HH / 2);
        int h2 = p % (HH / 2);
        float2 e = *(const float2*)&enc[h2 * 2];
        float2 q = *(const float2*)&pred[(size_t)i * HH + h2 * 2];
        __half2 hx = __floats2half2_rn(e.x + q.x, e.y + q.y);
        unsigned int u = *(unsigned int*)&hx, o;
        asm("tanh.approx.f16x2 %0, %1;" : "=r"(o) : "r"(u));
        *(unsigned int*)&g_joint[(size_t)(r0 + i) * HH + h2 * 2] = o;
    }
}

// ===========================================================================
// Main kernel: D = Joint(128 x 640, f16) @ W_fc(640 x 1024, f16) + bias,
// fused online log-softmax across 4 N-chunks of 256, mma.sync.m16n8k16.
// 256 threads = 8 warps: warp_m in {0,1} (64 rows), warp_n in {0..3} (64 cols).
// ===========================================================================
__device__ __forceinline__ float ex2sum2(float x0, float x1) {
    __half2 h = __floats2half2_rn(x0, x1);
    unsigned int u = *(unsigned int*)&h, o;
    asm("ex2.approx.f16x2 %0, %1;" : "=r"(o) : "r"(u));
    __half2 e = *(__half2*)&o;
    float2 f = __half22float2(e);
    return f.x + f.y;
}

#define SM_A 0
#define SM_B (128 * AROW * 2)                    // 165888
#define SM_RED (SM_B + 2 * 256 * BROW * 2)       // 190464
#define SM_SCM (SM_RED + 4 * 128 * 4)            // 192512
#define SM_RMAX (SM_SCM + 512)
#define SM_RSUM (SM_RMAX + 512)
#define SM_TOTAL (SM_RSUM + 512)                 // 194048

__global__ __launch_bounds__(256, 1) void joint_gemm(const float* __restrict__ bfc,
                                                     float* __restrict__ out) {
    extern __shared__ char sm[];
    __half* A_s = (__half*)(sm + SM_A);
    __half* B_s = (__half*)(sm + SM_B);
    float* red = (float*)(sm + SM_RED);    // [4][128]
    float* scm = (float*)(sm + SM_SCM);    // [128]
    float* rmax = (float*)(sm + SM_RMAX);  // [128]
    float* rsum = (float*)(sm + SM_RSUM);  // [128]

    const int tid = threadIdx.x;
    const int lane = tid & 31;
    const int warp = tid >> 5;
    const int wm = warp >> 2;   // 0..1
    const int wn = warp & 3;    // 0..3
    const int g = lane >> 2;    // 0..7
    const int t4 = lane & 3;    // 0..3
    const size_t row0 = (size_t)blockIdx.x * 128;

    // ---- load full A tile (128 x 640 f16) once via cp.async ----
    {
        const __half* src = g_joint + row0 * HH;
        for (int seg = tid; seg < 128 * 80; seg += 256) {
            int r = seg / 80, o = seg % 80;
            unsigned int sa =
                (unsigned int)__cvta_generic_to_shared(A_s + r * AROW) + o * 16;
            asm volatile("cp.async.ca.shared.global [%0], [%1], 16;" ::"r"(sa),
                         "l"(src + (size_t)r * HH + o * 8));
        }
        asm volatile("cp.async.commit_group;");
    }
    if (tid < 128) {
        rmax[tid] = -INFINITY;
        rsum[tid] = 0.f;
    }

    // B tile stage: [16 k][256 n] of chunk ch, k-step ks -> B_s[buf] as [n][k]
    auto stageB = [&](int ch, int ks, int buf) {
        const __half* src = g_w16t + (size_t)(ch * 256) * HH + ks * 16;
        __half* dstb = B_s + buf * (256 * BROW);
#pragma unroll
        for (int j = 0; j < 2; j++) {
            int seg = tid + 256 * j;
            int n = seg >> 1, h = seg & 1;
            unsigned int sa =
                (unsigned int)__cvta_generic_to_shared(dstb + n * BROW + h * 8);
            asm volatile("cp.async.ca.shared.global [%0], [%1], 16;" ::"r"(sa),
                         "l"(src + (size_t)n * HH + h * 8));
        }
        asm volatile("cp.async.commit_group;");
    };

    stageB(0, 0, 0);

    for (int ch = 0; ch < 4; ++ch) {
        float d[4][8][4];
#pragma unroll
        for (int mt = 0; mt < 4; mt++)
#pragma unroll
            for (int nt = 0; nt < 8; nt++)
#pragma unroll
                for (int q = 0; q < 4; q++) d[mt][nt][q] = 0.f;

        for (int ks = 0; ks < KT; ++ks) {
            if (ks + 1 < KT) {
                stageB(ch, ks + 1, (ks + 1) & 1);
                asm volatile("cp.async.wait_group 1;");
            } else {
                asm volatile("cp.async.wait_group 0;");
            }
            __syncthreads();

            const int k0 = ks * 16;
            const __half* Bb = B_s + (ks & 1) * (256 * BROW);

            unsigned int a[4][4];
#pragma unroll
            for (int mt = 0; mt < 4; mt++) {
                int r = wm * 64 + mt * 16 + g;
                const __half* ap = A_s + r * AROW + k0 + t4 * 2;
                a[mt][0] = *(const unsigned int*)ap;
                a[mt][1] = *(const unsigned int*)(ap + 8 * AROW);
                a[mt][2] = *(const unsigned int*)(ap + 8);
                a[mt][3] = *(const unsigned int*)(ap + 8 * AROW + 8);
            }
            unsigned int b[8][2];
#pragma unroll
            for (int nt = 0; nt < 8; nt++) {
                const __half* bp = Bb + (wn * 64 + nt * 8 + g) * BROW + t4 * 2;
                b[nt][0] = *(const unsigned int*)bp;
                b[nt][1] = *(const unsigned int*)(bp + 8);
            }
#pragma unroll
            for (int mt = 0; mt < 4; mt++)
#pragma unroll
                for (int nt = 0; nt < 8; nt++)
                    asm volatile(
                        "mma.sync.aligned.m16n8k16.row.col.f32.f16.f16.f32 "
                        "{%0,%1,%2,%3}, {%4,%5,%6,%7}, {%8,%9}, {%0,%1,%2,%3};"
                        : "+f"(d[mt][nt][0]), "+f"(d[mt][nt][1]),
                          "+f"(d[mt][nt][2]), "+f"(d[mt][nt][3])
                        : "r"(a[mt][0]), "r"(a[mt][1]), "r"(a[mt][2]),
                          "r"(a[mt][3]), "r"(b[nt][0]), "r"(b[nt][1]));
            __syncthreads();
        }

        // prefetch next chunk's first B tile under the epilogue
        if (ch < 3) stageB(ch + 1, 0, 0);

        // ---- bias ----
#pragma unroll
        for (int nt = 0; nt < 8; nt++) {
            int c = ch * 256 + wn * 64 + nt * 8 + t4 * 2;
            float b0 = __ldg(&bfc[c]), b1 = __ldg(&bfc[c + 1]);
#pragma unroll
            for (int mt = 0; mt < 4; mt++) {
                d[mt][nt][0] += b0;
                d[mt][nt][1] += b1;
                d[mt][nt][2] += b0;
                d[mt][nt][3] += b1;
            }
        }

        // ---- chunk row max ----
        float lm[4][2];
#pragma unroll
        for (int mt = 0; mt < 4; mt++) {
            float m0 = -INFINITY, m1 = -INFINITY;
#pragma unroll
            for (int nt = 0; nt < 8; nt++) {
                m0 = fmaxf(m0, fmaxf(d[mt][nt][0], d[mt][nt][1]));
                m1 = fmaxf(m1, fmaxf(d[mt][nt][2], d[mt][nt][3]));
            }
            lm[mt][0] = m0;
            lm[mt][1] = m1;
        }
#pragma unroll
        for (int mt = 0; mt < 4; mt++)
#pragma unroll
            for (int h = 0; h < 2; h++) {
                float v = lm[mt][h];
                v = fmaxf(v, __shfl_xor_sync(0xffffffffu, v, 1));
                v = fmaxf(v, __shfl_xor_sync(0xffffffffu, v, 2));
                lm[mt][h] = v;
            }
        if (t4 == 0) {
#pragma unroll
            for (int mt = 0; mt < 4; mt++)
#pragma unroll
                for (int h = 0; h < 2; h++)
                    red[wn * 128 + wm * 64 + mt * 16 + h * 8 + g] = lm[mt][h];
        }
        __syncthreads();
        if (tid < 128)
            scm[tid] = fmaxf(fmaxf(red[tid], red[128 + tid]),
                             fmaxf(red[256 + tid], red[384 + tid]));
        __syncthreads();

        // ---- chunk sum of exp (f16x2 ex2) ----
        float ls[4][2];
#pragma unroll
        for (int mt = 0; mt < 4; mt++)
#pragma unroll
            for (int h = 0; h < 2; h++) {
                float cm = scm[wm * 64 + mt * 16 + h * 8 + g];
                float s = 0.f;
#pragma unroll
                for (int nt = 0; nt < 8; nt++)
                    s += ex2sum2((d[mt][nt][2 * h] - cm) * L2E,
                                 (d[mt][nt][2 * h + 1] - cm) * L2E);
                ls[mt][h] = s;
            }
#pragma unroll
        for (int mt = 0; mt < 4; mt++)
#pragma unroll
            for (int h = 0; h < 2; h++) {
                float v = ls[mt][h];
                v += __shfl_xor_sync(0xffffffffu, v, 1);
                v += __shfl_xor_sync(0xffffffffu, v, 2);
                ls[mt][h] = v;
            }
        if (t4 == 0) {
#pragma unroll
            for (int mt = 0; mt < 4; mt++)
#pragma unroll
                for (int h = 0; h < 2; h++)
                    red[wn * 128 + wm * 64 + mt * 16 + h * 8 + g] = ls[mt][h];
        }
        __syncthreads();
        if (tid < 128) {
            float cs = red[tid] + red[128 + tid] + red[256 + tid] + red[384 + tid];
            float mo = rmax[tid];
            float mn = fmaxf(mo, scm[tid]);
            rsum[tid] = rsum[tid] * exp2f((mo - mn) * L2E) +
                        cs * exp2f((scm[tid] - mn) * L2E);
            rmax[tid] = mn;
        }

        // ---- store f16 logits to global scratch ----
#pragma unroll
        for (int mt = 0; mt < 4; mt++)
#pragma unroll
            for (int h = 0; h < 2; h++) {
                size_t r = row0 + wm * 64 + mt * 16 + h * 8 + g;
#pragma unroll
                for (int nt = 0; nt < 8; nt++) {
                    int c = ch * 256 + wn * 64 + nt * 8 + t4 * 2;
                    __half2 hv =
                        __floats2half2_rn(d[mt][nt][2 * h], d[mt][nt][2 * h + 1]);
                    *(unsigned int*)&g_logits[r * VV + c] = *(unsigned int*)&hv;
                }
            }
        __syncthreads();
    }

    // ---- finalize: rls then normalize (L2-hot re-read) ----
    if (tid < 128) scm[tid] = logf(rsum[tid]) + rmax[tid];
    __syncthreads();

    for (int idx = tid; idx < 128 * 512; idx += 256) {
        int r = idx >> 9;
        int c2 = idx & 511;
        unsigned int v = *(const unsigned int*)&g_logits[(row0 + r) * VV + c2 * 2];
        __half2 h = *(__half2*)&v;
        float2 f = __half22float2(h);
        float rls = scm[r];
        float2 o;
        o.x = f.x - rls;
        o.y = f.y - rls;
        *(float2*)&out[(row0 + r) * VV + c2 * 2] = o;
    }
}

// ===========================================================================
extern "C" void kernel_launch(void* const* d_in, const int* in_sizes, int n_in,
                              void* d_out, int out_size) {
    const float* enc_out = (const float*)d_in[0];
    const float* pred_out = (const float*)d_in[1];
    const float* W_enc = (const float*)d_in[2];
    const float* b_enc = (const float*)d_in[3];
    const float* W_pred = (const float*)d_in[4];
    const float* b_pred = (const float*)d_in[5];
    const float* W_fc = (const float*)d_in[6];
    const float* b_fc = (const float*)d_in[7];
    float* out = (float*)d_out;

    static int smem_set = 0;
    if (!smem_set) {
        cudaFuncSetAttribute(joint_gemm, cudaFuncAttributeMaxDynamicSharedMemorySize,
                             SM_TOTAL);
        smem_set = 1;
    }

    convert_wfc<<<dim3(VV / 32, HH / 32), 256>>>(W_fc);
    proj_gemm<<<dim3((BB * TT) / 64, HH / 64, 5), 256>>>(enc_out, W_enc, 0);
    proj_gemm<<<dim3((BB * UU) / 64, HH / 64, 5), 256>>>(pred_out, W_pred, 1);
    proj_reduce<<<(BB * TT * HH + BB * UU * HH) / 256, 256>>>(b_enc, b_pred);
    tanh_joint<<<MTOT / 32, 256>>>();
    joint_gemm<<<MTOT / 128, 256, SM_TOTAL>>>(b_fc, out);
}

// round 4
// speedup vs baseline: 2.7554x; 1.1813x over previous
#include <cuda_runtime.h>
#include <cuda_fp16.h>
#include <math.h>
#include <stdint.h>

#define BB 4
#define TT 256
#define UU 64
#define DD 640
#define HH 640
#define VV 1024
#define MTOT (BB*TT*UU)   // 65536
#define L2E 1.4426950408889634f

#define AROW 648          // f16 units per A row in SMEM
#define BROW 24           // f16 units per B row in SMEM (16 + 8 pad)
#define BBUF (256*BROW*2) // bytes per B stage = 12288
#define NSTEP 160         // 4 chunks x 40 k-steps

// ---- static device scratch ----
__device__ float  g_enc[BB*TT*HH];
__device__ float  g_pred[BB*UU*HH];
__device__ float  g_part[5*BB*TT*HH];
__device__ float  g_partp[5*BB*UU*HH];
__device__ __half g_w16t[VV*HH];                 // W_fc^T f16: [n][k]
__device__ __half g_joint[(size_t)MTOT*HH];      // tanh(enc+pred) f16
__device__ __half g_logits[(size_t)MTOT*VV];     // unnormalized logits f16

__device__ __forceinline__ uint32_t smem_u32(const void* p) {
    uint32_t a;
    asm("{ .reg .u64 t; cvta.to.shared.u64 t, %1; cvt.u32.u64 %0, t; }"
        : "=r"(a) : "l"(p));
    return a;
}
__device__ __forceinline__ void cpasync16(uint32_t dst, const void* src) {
    asm volatile("cp.async.ca.shared.global [%0], [%1], 16;" ::"r"(dst), "l"(src));
}
#define CP_COMMIT() asm volatile("cp.async.commit_group;")
#define CP_WAIT(n) asm volatile("cp.async.wait_group %0;" ::"n"(n))

__device__ __forceinline__ void ldsm_x4(uint32_t* r, uint32_t addr) {
    asm volatile("ldmatrix.sync.aligned.m8n8.x4.shared.b16 {%0,%1,%2,%3}, [%4];"
                 : "=r"(r[0]), "=r"(r[1]), "=r"(r[2]), "=r"(r[3]) : "r"(addr));
}
__device__ __forceinline__ float ex2sum2(float x0, float x1) {
    __half2 h = __floats2half2_rn(x0, x1);
    unsigned int u = *(unsigned int*)&h, o;
    asm("ex2.approx.f16x2 %0, %1;" : "=r"(o) : "r"(u));
    float2 f = __half22float2(*(__half2*)&o);
    return f.x + f.y;
}

// ===========================================================================
// W_fc fp32 [k][n] -> f16 transposed [n][k]
// ===========================================================================
__global__ __launch_bounds__(256) void convert_wfc(const float* __restrict__ Wfc) {
    __shared__ float t[32][33];
    int n0 = blockIdx.x * 32, k0 = blockIdx.y * 32;
    int tx = threadIdx.x & 31, ty = threadIdx.x >> 5;
#pragma unroll
    for (int j = 0; j < 4; j++)
        t[ty + 8 * j][tx] = Wfc[(size_t)(k0 + ty + 8 * j) * VV + n0 + tx];
    __syncthreads();
#pragma unroll
    for (int j = 0; j < 4; j++)
        g_w16t[(size_t)(n0 + ty + 8 * j) * HH + k0 + tx] = __float2half(t[tx][ty + 8 * j]);
}

// ===========================================================================
// Projection GEMM (split-K by 5) + reduce
// ===========================================================================
__global__ __launch_bounds__(256) void proj_gemm(const float* __restrict__ X,
                                                 const float* __restrict__ W, int which) {
    float* C = which ? g_partp : g_part;
    const int Mrows = which ? (BB * UU) : (BB * TT);
    __shared__ float As[16][65];
    __shared__ float Bs[16][65];
    const int tid = threadIdx.x;
    const int bm = blockIdx.x * 64, bn = blockIdx.y * 64, kz = blockIdx.z;
    const int ty = tid / 16, tx = tid % 16;
    float c[4][4];
#pragma unroll
    for (int i = 0; i < 4; i++)
#pragma unroll
        for (int j = 0; j < 4; j++) c[i][j] = 0.f;
    for (int k0 = kz * 128; k0 < kz * 128 + 128; k0 += 16) {
        for (int l = tid; l < 64 * 16; l += 256) {
            int row = l >> 4, kk = l & 15;
            As[kk][row] = X[(size_t)(bm + row) * DD + k0 + kk];
        }
        for (int l = tid; l < 16 * 64; l += 256) {
            int kk = l >> 6, col = l & 63;
            Bs[kk][col] = W[(size_t)(k0 + kk) * HH + bn + col];
        }
        __syncthreads();
#pragma unroll
        for (int kk = 0; kk < 16; kk++) {
            float a[4], b[4];
#pragma unroll
            for (int i = 0; i < 4; i++) a[i] = As[kk][ty * 4 + i];
#pragma unroll
            for (int j = 0; j < 4; j++) b[j] = Bs[kk][tx * 4 + j];
#pragma unroll
            for (int i = 0; i < 4; i++)
#pragma unroll
                for (int j = 0; j < 4; j++) c[i][j] += a[i] * b[j];
        }
        __syncthreads();
    }
    float* Cz = C + (size_t)kz * Mrows * HH;
#pragma unroll
    for (int i = 0; i < 4; i++)
#pragma unroll
        for (int j = 0; j < 4; j++)
            Cz[(size_t)(bm + ty * 4 + i) * HH + bn + tx * 4 + j] = c[i][j];
}

__global__ __launch_bounds__(256) void proj_reduce(const float* __restrict__ b_enc,
                                                   const float* __restrict__ b_pred) {
    int idx = blockIdx.x * 256 + threadIdx.x;
    const int encN = BB * TT * HH, predN = BB * UU * HH;
    if (idx < encN) {
        float s = b_enc[idx % HH];
#pragma unroll
        for (int z = 0; z < 5; z++) s += g_part[(size_t)z * encN + idx];
        g_enc[idx] = s;
    } else {
        int j = idx - encN;
        if (j < predN) {
            float s = b_pred[j % HH];
#pragma unroll
            for (int z = 0; z < 5; z++) s += g_partp[(size_t)z * predN + j];
            g_pred[j] = s;
        }
    }
}

// ===========================================================================
// Joint tanh -> f16
// ===========================================================================
__global__ __launch_bounds__(256) void tanh_joint() {
    const int r0 = blockIdx.x * 32;
    const float* enc = g_enc + (size_t)(r0 / UU) * HH;
    const float* pred = g_pred + ((size_t)(r0 / (TT * UU)) * UU + (r0 % UU)) * HH;
    for (int p = threadIdx.x; p < 32 * (HH / 2); p += 256) {
        int i = p / (HH / 2);
        int h2 = p % (HH / 2);
        float2 e = *(const float2*)&enc[h2 * 2];
        float2 q = *(const float2*)&pred[(size_t)i * HH + h2 * 2];
        __half2 hx = __floats2half2_rn(e.x + q.x, e.y + q.y);
        unsigned int u = *(unsigned int*)&hx, o;
        asm("tanh.approx.f16x2 %0, %1;" : "=r"(o) : "r"(u));
        *(unsigned int*)&g_joint[(size_t)(r0 + i) * HH + h2 * 2] = o;
    }
}

// ===========================================================================
// Main kernel: mma.sync m16n8k16, ldmatrix fragments, 3-stage cp.async
// pipeline with ONE __syncthreads per k-step. 256 threads = 8 warps
// (wm 0..1 x wn 0..3), warp tile 64x64, CTA tile 128 x 256-chunk x K640.
// ===========================================================================
#define SM_A 0
#define SM_B (128 * AROW * 2)          // 165888
#define SM_RED (SM_B + 3 * BBUF)       // 202752
#define SM_SCM (SM_RED + 2048)         // 204800
#define SM_RMAX (SM_SCM + 512)         // 205312
#define SM_RSUM (SM_RMAX + 512)        // 205824
#define SM_TOTAL (SM_RSUM + 512)       // 206336

__global__ __launch_bounds__(256, 1) void joint_gemm(const float* __restrict__ bfc,
                                                     float* __restrict__ out) {
    extern __shared__ char smc[];
    const uint32_t sbase = smem_u32(smc);
    float* red = (float*)(smc + SM_RED);
    float* scm = (float*)(smc + SM_SCM);
    float* rmax = (float*)(smc + SM_RMAX);
    float* rsum = (float*)(smc + SM_RSUM);

    const int tid = threadIdx.x;
    const int lane = tid & 31;
    const int warp = tid >> 5;
    const int wm = warp >> 2;   // 0..1
    const int wn = warp & 3;    // 0..3
    const int g = lane >> 2;    // 0..7
    const int t4 = lane & 3;    // 0..3
    const size_t row0 = (size_t)blockIdx.x * 128;

    // ---- stage B tile for global k-step gi into buffer buf ----
    auto loadB = [&](int gi, int buf) {
        int ch = gi / 40, ks = gi % 40;
        const __half* src = g_w16t + (size_t)(ch * 256 + tid) * HH + ks * 16;
        uint32_t dst = sbase + SM_B + buf * BBUF + tid * (BROW * 2);
        cpasync16(dst, src);
        cpasync16(dst + 16, src + 8);
    };

    // ---- prologue: A tile + first two B stages ----
    {
        const __half* asrc = g_joint + row0 * HH;
        for (int seg = tid; seg < 128 * 80; seg += 256) {
            int r = seg / 80, o = seg % 80;
            uint32_t sa = sbase + SM_A + r * (AROW * 2) + o * 16;
            cpasync16(sa, asrc + (size_t)r * HH + o * 8);
        }
        loadB(0, 0);
        CP_COMMIT();            // group: A + stage0
        loadB(1, 1);
        CP_COMMIT();            // group: stage1
    }
    if (tid < 128) {
        rmax[tid] = -INFINITY;
        rsum[tid] = 0.f;
    }

    float d[4][8][4];
#pragma unroll
    for (int mt = 0; mt < 4; mt++)
#pragma unroll
        for (int nt = 0; nt < 8; nt++)
#pragma unroll
            for (int q = 0; q < 4; q++) d[mt][nt][q] = 0.f;

    // precomputed ldmatrix lane addressing
    const uint32_t a_lane_row = (uint32_t)(wm * 64 + (lane & 15));
    const uint32_t a_lane_coloff = (uint32_t)((lane >> 4) << 3);
    const uint32_t b_lane_n = (uint32_t)(wn * 64 + (lane & 7) + ((lane >> 4) << 3));
    const uint32_t b_lane_koff = (uint32_t)(((lane >> 3) & 1) << 3);

    for (int gi = 0; gi < NSTEP; gi++) {
        if (gi == NSTEP - 1) { CP_WAIT(0); } else { CP_WAIT(1); }
        __syncthreads();
        if (gi + 2 < NSTEP) {
            loadB(gi + 2, (gi + 2) % 3);
            CP_COMMIT();
        }

        const int ks = gi % 40;
        const int buf = gi % 3;
        const uint32_t abase =
            sbase + SM_A + (a_lane_row * AROW + (uint32_t)(ks * 16) + a_lane_coloff) * 2;
        const uint32_t bbase =
            sbase + SM_B + buf * BBUF + (b_lane_n * BROW + b_lane_koff) * 2;

        uint32_t a[4][4];
#pragma unroll
        for (int mt = 0; mt < 4; mt++) ldsm_x4(a[mt], abase + mt * 16 * (AROW * 2));

#pragma unroll
        for (int p = 0; p < 4; p++) {
            uint32_t b[4];
            ldsm_x4(b, bbase + p * 16 * (BROW * 2));
#pragma unroll
            for (int mt = 0; mt < 4; mt++) {
                asm volatile(
                    "mma.sync.aligned.m16n8k16.row.col.f32.f16.f16.f32 "
                    "{%0,%1,%2,%3}, {%4,%5,%6,%7}, {%8,%9}, {%0,%1,%2,%3};"
                    : "+f"(d[mt][2 * p][0]), "+f"(d[mt][2 * p][1]),
                      "+f"(d[mt][2 * p][2]), "+f"(d[mt][2 * p][3])
                    : "r"(a[mt][0]), "r"(a[mt][1]), "r"(a[mt][2]), "r"(a[mt][3]),
                      "r"(b[0]), "r"(b[1]));
                asm volatile(
                    "mma.sync.aligned.m16n8k16.row.col.f32.f16.f16.f32 "
                    "{%0,%1,%2,%3}, {%4,%5,%6,%7}, {%8,%9}, {%0,%1,%2,%3};"
                    : "+f"(d[mt][2 * p + 1][0]), "+f"(d[mt][2 * p + 1][1]),
                      "+f"(d[mt][2 * p + 1][2]), "+f"(d[mt][2 * p + 1][3])
                    : "r"(a[mt][0]), "r"(a[mt][1]), "r"(a[mt][2]), "r"(a[mt][3]),
                      "r"(b[2]), "r"(b[3]));
            }
        }

        if (ks == 39) {
            const int ch = gi / 40;
            // ---- bias ----
#pragma unroll
            for (int nt = 0; nt < 8; nt++) {
                int c = ch * 256 + wn * 64 + nt * 8 + t4 * 2;
                float b0 = __ldg(&bfc[c]), b1 = __ldg(&bfc[c + 1]);
#pragma unroll
                for (int mt = 0; mt < 4; mt++) {
                    d[mt][nt][0] += b0;
                    d[mt][nt][1] += b1;
                    d[mt][nt][2] += b0;
                    d[mt][nt][3] += b1;
                }
            }
            // ---- chunk row max ----
            float lm[4][2];
#pragma unroll
            for (int mt = 0; mt < 4; mt++) {
                float m0 = -INFINITY, m1 = -INFINITY;
#pragma unroll
                for (int nt = 0; nt < 8; nt++) {
                    m0 = fmaxf(m0, fmaxf(d[mt][nt][0], d[mt][nt][1]));
                    m1 = fmaxf(m1, fmaxf(d[mt][nt][2], d[mt][nt][3]));
                }
                lm[mt][0] = m0;
                lm[mt][1] = m1;
            }
#pragma unroll
            for (int mt = 0; mt < 4; mt++)
#pragma unroll
                for (int h = 0; h < 2; h++) {
                    float v = lm[mt][h];
                    v = fmaxf(v, __shfl_xor_sync(0xffffffffu, v, 1));
                    v = fmaxf(v, __shfl_xor_sync(0xffffffffu, v, 2));
                    lm[mt][h] = v;
                }
            if (t4 == 0) {
#pragma unroll
                for (int mt = 0; mt < 4; mt++)
#pragma unroll
                    for (int h = 0; h < 2; h++)
                        red[wn * 128 + wm * 64 + mt * 16 + h * 8 + g] = lm[mt][h];
            }
            __syncthreads();
            if (tid < 128)
                scm[tid] = fmaxf(fmaxf(red[tid], red[128 + tid]),
                                 fmaxf(red[256 + tid], red[384 + tid]));
            __syncthreads();

            // ---- chunk sum of exp ----
            float ls[4][2];
#pragma unroll
            for (int mt = 0; mt < 4; mt++)
#pragma unroll
                for (int h = 0; h < 2; h++) {
                    float cm = scm[wm * 64 + mt * 16 + h * 8 + g];
                    float s = 0.f;
#pragma unroll
                    for (int nt = 0; nt < 8; nt++)
                        s += ex2sum2((d[mt][nt][2 * h] - cm) * L2E,
                                     (d[mt][nt][2 * h + 1] - cm) * L2E);
                    ls[mt][h] = s;
                }
#pragma unroll
            for (int mt = 0; mt < 4; mt++)
#pragma unroll
                for (int h = 0; h < 2; h++) {
                    float v = ls[mt][h];
                    v += __shfl_xor_sync(0xffffffffu, v, 1);
                    v += __shfl_xor_sync(0xffffffffu, v, 2);
                    ls[mt][h] = v;
                }
            if (t4 == 0) {
#pragma unroll
                for (int mt = 0; mt < 4; mt++)
#pragma unroll
                    for (int h = 0; h < 2; h++)
                        red[wn * 128 + wm * 64 + mt * 16 + h * 8 + g] = ls[mt][h];
            }
            __syncthreads();
            if (tid < 128) {
                float cs = red[tid] + red[128 + tid] + red[256 + tid] + red[384 + tid];
                float mo = rmax[tid];
                float mn = fmaxf(mo, scm[tid]);
                rsum[tid] = rsum[tid] * exp2f((mo - mn) * L2E) +
                            cs * exp2f((scm[tid] - mn) * L2E);
                rmax[tid] = mn;
            }

            // ---- store f16 logits + reset accumulators ----
#pragma unroll
            for (int mt = 0; mt < 4; mt++)
#pragma unroll
                for (int h = 0; h < 2; h++) {
                    size_t r = row0 + wm * 64 + mt * 16 + h * 8 + g;
#pragma unroll
                    for (int nt = 0; nt < 8; nt++) {
                        int c = ch * 256 + wn * 64 + nt * 8 + t4 * 2;
                        __half2 hv =
                            __floats2half2_rn(d[mt][nt][2 * h], d[mt][nt][2 * h + 1]);
                        *(unsigned int*)&g_logits[r * VV + c] = *(unsigned int*)&hv;
                    }
                }
#pragma unroll
            for (int mt = 0; mt < 4; mt++)
#pragma unroll
                for (int nt = 0; nt < 8; nt++)
#pragma unroll
                    for (int q = 0; q < 4; q++) d[mt][nt][q] = 0.f;
        }
    }

    // ---- finalize: rls then normalize ----
    __syncthreads();
    if (tid < 128) scm[tid] = logf(rsum[tid]) + rmax[tid];
    __syncthreads();

    for (int p = tid; p < 128 * 256; p += 256) {
        int r = p >> 8;
        int c4 = p & 255;
        float rls = scm[r];
        uint2 lv = *(const uint2*)&g_logits[(row0 + r) * VV + c4 * 4];
        float2 f0 = __half22float2(*(__half2*)&lv.x);
        float2 f1 = __half22float2(*(__half2*)&lv.y);
        float4 o;
        o.x = f0.x - rls;
        o.y = f0.y - rls;
        o.z = f1.x - rls;
        o.w = f1.y - rls;
        *(float4*)&out[(row0 + r) * VV + c4 * 4] = o;
    }
}

// ===========================================================================
extern "C" void kernel_launch(void* const* d_in, const int* in_sizes, int n_in,
                              void* d_out, int out_size) {
    const float* enc_out = (const float*)d_in[0];
    const float* pred_out = (const float*)d_in[1];
    const float* W_enc = (const float*)d_in[2];
    const float* b_enc = (const float*)d_in[3];
    const float* W_pred = (const float*)d_in[4];
    const float* b_pred = (const float*)d_in[5];
    const float* W_fc = (const float*)d_in[6];
    const float* b_fc = (const float*)d_in[7];
    float* out = (float*)d_out;

    cudaFuncSetAttribute(joint_gemm, cudaFuncAttributeMaxDynamicSharedMemorySize,
                         SM_TOTAL);

    convert_wfc<<<dim3(VV / 32, HH / 32), 256>>>(W_fc);
    proj_gemm<<<dim3((BB * TT) / 64, HH / 64, 5), 256>>>(enc_out, W_enc, 0);
    proj_gemm<<<dim3((BB * UU) / 64, HH / 64, 5), 256>>>(pred_out, W_pred, 1);
    proj_reduce<<<(BB * TT * HH + BB * UU * HH) / 256, 256>>>(b_enc, b_pred);
    tanh_joint<<<MTOT / 32, 256>>>();
    joint_gemm<<<MTOT / 128, 256, SM_TOTAL>>>(b_fc, out);
}